// round 8
// baseline (speedup 1.0000x reference)
#include <cuda_runtime.h>
#include <cuda_bf16.h>
#include <mma.h>
#include <math.h>

using namespace nvcuda;

// Problem constants
#define Bsz 1024
#define Nn  128
#define Dd  1024
#define OBS 256
#define Hh  256
#define SIGMA 0.05f
#define SUB  128              // one noise row per batch row (saturation-safe, validated R7)

#define NBLK 128
#define NTHR 256

// Device globals (no allocation allowed)
__device__ __nv_bfloat16 g_w1b[OBS * Hh];
__device__ __nv_bfloat16 g_w2b[Hh * Hh];
__device__ __nv_bfloat16 g_w3b[Hh * Dd];
__device__ __nv_bfloat16 g_wv1b[OBS * Hh];
__device__ __nv_bfloat16 g_obsb[Bsz * OBS];
__device__ __nv_bfloat16 g_h1b[Bsz * Hh];
__device__ __nv_bfloat16 g_h2b[Bsz * Hh];
__device__ float g_logits[Bsz * Dd];
__device__ float g_vpre[Bsz * Hh];
__device__ unsigned long long g_sum;
__device__ unsigned g_count[8];   // zero-init; each barrier resets its counter on release
__device__ unsigned g_sense[8];   // monotonically increasing generation

// ---------------------------------------------------------------------------
// Sense-reversing grid barrier. Safe: 128 blocks <= 148 SMs, all resident.
// ---------------------------------------------------------------------------
__device__ __forceinline__ void grid_barrier(int i) {
    __threadfence();          // publish this thread's writes before arrival
    __syncthreads();
    if (threadIdx.x == 0) {
        unsigned gen = atomicAdd(&g_sense[i], 0u);
        if (atomicAdd(&g_count[i], 1u) == NBLK - 1) {
            g_count[i] = 0;
            __threadfence();
            atomicAdd(&g_sense[i], 1u);
        } else {
            while (atomicAdd(&g_sense[i], 0u) == gen) __nanosleep(64);
        }
        __threadfence();
    }
    __syncthreads();
}

// ---------------------------------------------------------------------------
// cp.async helpers
// ---------------------------------------------------------------------------
__device__ __forceinline__ void cp16(void* smem_dst, const void* gmem_src) {
    unsigned saddr = (unsigned)__cvta_generic_to_shared(smem_dst);
    asm volatile("cp.async.cg.shared.global [%0], [%1], 16;\n"
                 :: "r"(saddr), "l"(gmem_src));
}
__device__ __forceinline__ void cp_commit() {
    asm volatile("cp.async.commit_group;\n");
}
template <int N>
__device__ __forceinline__ void cp_wait() {
    asm volatile("cp.async.wait_group %0;\n" :: "n"(N));
}

// ---------------------------------------------------------------------------
// 64x64 GEMM tile (K=256, 4 x BK=64 double-buffered). 8 warps as 2x4.
// smem layout in dsm: sA 2x(64x72) bf16 @0 (18432B), sB 2x(64x72) @18432.
// Epilogue staged via dsm as fp32 (pitch 68).
// ---------------------------------------------------------------------------
__device__ __forceinline__ void gemm_tile64(
    const __nv_bfloat16* __restrict__ A, int row0,
    const __nv_bfloat16* __restrict__ B, int ldB, int cb,
    const float* __restrict__ bias, void* __restrict__ C,
    int ldC, int act, int obf, char* dsm)
{
    __nv_bfloat16* sA = reinterpret_cast<__nv_bfloat16*>(dsm);
    __nv_bfloat16* sB = reinterpret_cast<__nv_bfloat16*>(dsm + 18432);
    const int tid = threadIdx.x;
    const int warp = tid >> 5, wr = warp >> 2, wc = warp & 3;

    auto stage = [&](int buf, int k0) {
        #pragma unroll
        for (int i = 0; i < 2; i++) {
            int q = tid + i * 256;
            int r = q >> 3, c8 = q & 7;
            cp16(&sA[buf * 4608 + r * 72 + c8 * 8],
                 A + (size_t)(row0 + r) * 256 + k0 + c8 * 8);
            cp16(&sB[buf * 4608 + r * 72 + c8 * 8],
                 B + (size_t)(k0 + r) * ldB + cb + c8 * 8);
        }
        cp_commit();
    };

    wmma::fragment<wmma::accumulator, 16, 16, 16, float> acc0, acc1;
    wmma::fill_fragment(acc0, 0.0f);
    wmma::fill_fragment(acc1, 0.0f);

    stage(0, 0);
    #pragma unroll
    for (int t = 0; t < 4; t++) {
        if (t + 1 < 4) { stage((t + 1) & 1, (t + 1) * 64); cp_wait<1>(); }
        else cp_wait<0>();
        __syncthreads();
        const __nv_bfloat16* cA = sA + (t & 1) * 4608;
        const __nv_bfloat16* cB = sB + (t & 1) * 4608;
        #pragma unroll
        for (int kk = 0; kk < 4; kk++) {
            const int k16 = kk * 16;
            wmma::fragment<wmma::matrix_a, 16, 16, 16, __nv_bfloat16, wmma::row_major> a0, a1;
            wmma::fragment<wmma::matrix_b, 16, 16, 16, __nv_bfloat16, wmma::row_major> bf;
            wmma::load_matrix_sync(a0, cA + (wr * 32) * 72 + k16, 72);
            wmma::load_matrix_sync(a1, cA + (wr * 32 + 16) * 72 + k16, 72);
            wmma::load_matrix_sync(bf, cB + k16 * 72 + wc * 16, 72);
            wmma::mma_sync(acc0, a0, bf, acc0);
            wmma::mma_sync(acc1, a1, bf, acc1);
        }
        __syncthreads();
    }

    float* sC = reinterpret_cast<float*>(dsm);
    wmma::store_matrix_sync(sC + (wr * 32) * 68 + wc * 16, acc0, 68, wmma::mem_row_major);
    wmma::store_matrix_sync(sC + (wr * 32 + 16) * 68 + wc * 16, acc1, 68, wmma::mem_row_major);
    __syncthreads();

    #pragma unroll
    for (int i = 0; i < 4; i++) {
        int q = tid + i * 256;
        int r = q >> 4, c4 = q & 15;
        float4 v = *reinterpret_cast<const float4*>(&sC[r * 68 + c4 * 4]);
        float4 bb = *reinterpret_cast<const float4*>(bias + cb + c4 * 4);
        v.x += bb.x; v.y += bb.y; v.z += bb.z; v.w += bb.w;
        if (act) { v.x = tanhf(v.x); v.y = tanhf(v.y); v.z = tanhf(v.z); v.w = tanhf(v.w); }
        if (obf) {
            __nv_bfloat162 p0 = __floats2bfloat162_rn(v.x, v.y);
            __nv_bfloat162 p1 = __floats2bfloat162_rn(v.z, v.w);
            uint2 u = { *reinterpret_cast<unsigned*>(&p0), *reinterpret_cast<unsigned*>(&p1) };
            *reinterpret_cast<uint2*>(
                reinterpret_cast<__nv_bfloat16*>(C) + (size_t)(row0 + r) * ldC + cb + c4 * 4) = u;
        } else {
            *reinterpret_cast<float4*>(
                reinterpret_cast<float*>(C) + (size_t)(row0 + r) * ldC + cb + c4 * 4) = v;
        }
    }
    __syncthreads();   // dsm reuse safety for caller
}

// ---------------------------------------------------------------------------
// 64x128 GEMM tile for the logits stage (B = [256,1024] bf16). 8 warps as 2x4,
// warp tile 32x32 (2x2 fragments). smem: sA 2x(64x72) @0; sB 2x(64x136) @18432.
// Output: g_logits fp32 with +bias, no act.
// ---------------------------------------------------------------------------
__device__ __forceinline__ void gemm_tile64x128(
    const __nv_bfloat16* __restrict__ A, int row0,
    const __nv_bfloat16* __restrict__ B, int cb,
    const float* __restrict__ bias, float* __restrict__ C, char* dsm)
{
    __nv_bfloat16* sA = reinterpret_cast<__nv_bfloat16*>(dsm);
    __nv_bfloat16* sB = reinterpret_cast<__nv_bfloat16*>(dsm + 18432);
    const int tid = threadIdx.x;
    const int warp = tid >> 5, wr = warp >> 2, wc = warp & 3;

    auto stage = [&](int buf, int k0) {
        #pragma unroll
        for (int i = 0; i < 2; i++) {
            int q = tid + i * 256;
            int r = q >> 3, c8 = q & 7;
            cp16(&sA[buf * 4608 + r * 72 + c8 * 8],
                 A + (size_t)(row0 + r) * 256 + k0 + c8 * 8);
        }
        #pragma unroll
        for (int i = 0; i < 4; i++) {
            int q = tid + i * 256;
            int r = q >> 4, c8 = q & 15;
            cp16(&sB[buf * 8704 + r * 136 + c8 * 8],
                 B + (size_t)(k0 + r) * Dd + cb + c8 * 8);
        }
        cp_commit();
    };

    wmma::fragment<wmma::accumulator, 16, 16, 16, float> acc[2][2];
    #pragma unroll
    for (int i = 0; i < 2; i++)
        #pragma unroll
        for (int j = 0; j < 2; j++) wmma::fill_fragment(acc[i][j], 0.0f);

    stage(0, 0);
    #pragma unroll
    for (int t = 0; t < 4; t++) {
        if (t + 1 < 4) { stage((t + 1) & 1, (t + 1) * 64); cp_wait<1>(); }
        else cp_wait<0>();
        __syncthreads();
        const __nv_bfloat16* cA = sA + (t & 1) * 4608;
        const __nv_bfloat16* cB = sB + (t & 1) * 8704;
        #pragma unroll
        for (int kk = 0; kk < 4; kk++) {
            const int k16 = kk * 16;
            wmma::fragment<wmma::matrix_a, 16, 16, 16, __nv_bfloat16, wmma::row_major> a0, a1;
            wmma::fragment<wmma::matrix_b, 16, 16, 16, __nv_bfloat16, wmma::row_major> b0, b1;
            wmma::load_matrix_sync(a0, cA + (wr * 32) * 72 + k16, 72);
            wmma::load_matrix_sync(a1, cA + (wr * 32 + 16) * 72 + k16, 72);
            wmma::load_matrix_sync(b0, cB + k16 * 136 + wc * 32, 136);
            wmma::load_matrix_sync(b1, cB + k16 * 136 + wc * 32 + 16, 136);
            wmma::mma_sync(acc[0][0], a0, b0, acc[0][0]);
            wmma::mma_sync(acc[0][1], a0, b1, acc[0][1]);
            wmma::mma_sync(acc[1][0], a1, b0, acc[1][0]);
            wmma::mma_sync(acc[1][1], a1, b1, acc[1][1]);
        }
        __syncthreads();
    }

    float* sC = reinterpret_cast<float*>(dsm);   // 64 x 132 fp32 = 33792 B
    #pragma unroll
    for (int mi = 0; mi < 2; mi++)
        #pragma unroll
        for (int ni = 0; ni < 2; ni++)
            wmma::store_matrix_sync(sC + (wr * 32 + mi * 16) * 132 + wc * 32 + ni * 16,
                                    acc[mi][ni], 132, wmma::mem_row_major);
    __syncthreads();

    #pragma unroll
    for (int i = 0; i < 8; i++) {
        int q = tid + i * 256;               // 0..2047 float4 positions
        int r = q >> 5, c4 = q & 31;
        float4 v = *reinterpret_cast<const float4*>(&sC[r * 132 + c4 * 4]);
        float4 bb = *reinterpret_cast<const float4*>(bias + cb + c4 * 4);
        v.x += bb.x; v.y += bb.y; v.z += bb.z; v.w += bb.w;
        *reinterpret_cast<float4*>(C + (size_t)(row0 + r) * Dd + cb + c4 * 4) = v;
    }
    __syncthreads();
}

// ---------------------------------------------------------------------------
// Persistent kernel: all phases with grid barriers.
// ---------------------------------------------------------------------------
extern __shared__ char dsm[];

__global__ __launch_bounds__(NTHR, 1) void persistent_kernel(
    const float* __restrict__ obs, const float* __restrict__ noise,
    const float* __restrict__ W1, const float* __restrict__ b1,
    const float* __restrict__ W2, const float* __restrict__ b2,
    const float* __restrict__ W3, const float* __restrict__ b3,
    const float* __restrict__ Wv1, const float* __restrict__ bv1,
    const float* __restrict__ Wv2, const float* __restrict__ bv2,
    float* __restrict__ out)
{
    const int tid = threadIdx.x;
    const int blk = blockIdx.x;
    const int warp = tid >> 5;
    const int lane = tid & 31;

    // ---- Phase 0: zero g_sum; convert weights + obs fp32 -> bf16 ----
    {
        int base = blk * NTHR + tid;             // 0..32767
        if (base == 0) g_sum = 0ULL;
        #pragma unroll
        for (int it = 0; it < 6; it++) {
            int idx = base + it * (NBLK * NTHR);
            if (idx >= 180224) break;
            const float* src; __nv_bfloat16* dst; int off;
            if      (idx <  16384) { src = W1;  dst = g_w1b;  off = idx; }
            else if (idx <  32768) { src = W2;  dst = g_w2b;  off = idx - 16384; }
            else if (idx <  98304) { src = W3;  dst = g_w3b;  off = idx - 32768; }
            else if (idx < 114688) { src = Wv1; dst = g_wv1b; off = idx - 98304; }
            else                   { src = obs; dst = g_obsb; off = idx - 114688; }
            float4 v = *reinterpret_cast<const float4*>(src + (size_t)off * 4);
            __nv_bfloat162 p0 = __floats2bfloat162_rn(v.x, v.y);
            __nv_bfloat162 p1 = __floats2bfloat162_rn(v.z, v.w);
            uint2 u = { *reinterpret_cast<unsigned*>(&p0), *reinterpret_cast<unsigned*>(&p1) };
            *reinterpret_cast<uint2*>(dst + (size_t)off * 4) = u;
        }
    }
    grid_barrier(0);

    // ---- Phase 1: h1 = tanh(obs@W1+b1) [bf16] | vpre = obs@Wv1+bv1 [fp32] ----
    {
        int rowTile = blk >> 3, colTile = blk & 7;     // 16 x 8 = 128 tiles
        if (colTile < 4)
            gemm_tile64(g_obsb, rowTile * 64, g_w1b, Hh, colTile * 64,
                        b1, g_h1b, Hh, 1, 1, dsm);
        else
            gemm_tile64(g_obsb, rowTile * 64, g_wv1b, Hh, (colTile - 4) * 64,
                        bv1, g_vpre, Hh, 0, 0, dsm);
    }
    grid_barrier(1);

    // ---- Phase 2: h2 = tanh(h1@W2+b2) [bf16]  (64 tiles; blocks 0..63) ----
    if (blk < 64) {
        int rowTile = blk >> 2, colTile = blk & 3;
        gemm_tile64(g_h1b, rowTile * 64, g_w2b, Hh, colTile * 64,
                    b2, g_h2b, Hh, 1, 1, dsm);
    }
    grid_barrier(2);

    // ---- Phase 3: logits = h2@W3+b3 [fp32]  (128 tiles of 64x128) ----
    {
        int rowTile = blk >> 3, colTile = blk & 7;
        gemm_tile64x128(g_h2b, rowTile * 64, g_w3b, colTile * 128, b3, g_logits, dsm);
    }
    grid_barrier(3);

    // ---- Phase 4: softmax + perturbed argmax, 8 rows per block ----
    {
        __shared__ float sv[8];
        __shared__ int si[8];
        for (int rr = 0; rr < 8; rr++) {
            int b = blk * 8 + rr;
            float4 x = *reinterpret_cast<const float4*>(g_logits + (size_t)b * Dd + tid * 4);

            float m = fmaxf(fmaxf(x.x, x.y), fmaxf(x.z, x.w));
            #pragma unroll
            for (int off = 16; off > 0; off >>= 1)
                m = fmaxf(m, __shfl_xor_sync(0xFFFFFFFFu, m, off));
            if (lane == 0) sv[warp] = m;
            __syncthreads();
            m = sv[0];
            #pragma unroll
            for (int w = 1; w < 8; w++) m = fmaxf(m, sv[w]);
            __syncthreads();

            float e0 = expf(x.x - m), e1 = expf(x.y - m);
            float e2 = expf(x.z - m), e3 = expf(x.w - m);
            float s = e0 + e1 + e2 + e3;
            #pragma unroll
            for (int off = 16; off > 0; off >>= 1)
                s += __shfl_xor_sync(0xFFFFFFFFu, s, off);
            if (lane == 0) sv[warp] = s;
            __syncthreads();
            s = sv[0];
            #pragma unroll
            for (int w = 1; w < 8; w++) s += sv[w];
            float inv = 1.f / s;
            __syncthreads();

            float4 nz = __ldcs(reinterpret_cast<const float4*>(
                noise + (size_t)b * Nn * Dd) + tid);
            float v0 = e0 * inv + SIGMA * nz.x;
            float v1 = e1 * inv + SIGMA * nz.y;
            float v2 = e2 * inv + SIGMA * nz.z;
            float v3 = e3 * inv + SIGMA * nz.w;
            int base = tid * 4;
            float best = v0; int bi = base;
            if (v1 > best) { best = v1; bi = base + 1; }
            if (v2 > best) { best = v2; bi = base + 2; }
            if (v3 > best) { best = v3; bi = base + 3; }
            #pragma unroll
            for (int off = 16; off > 0; off >>= 1) {
                float ov = __shfl_down_sync(0xFFFFFFFFu, best, off);
                int   oi = __shfl_down_sync(0xFFFFFFFFu, bi, off);
                if (ov > best || (ov == best && oi < bi)) { best = ov; bi = oi; }
            }
            if (lane == 0) { sv[warp] = best; si[warp] = bi; }
            __syncthreads();
            if (tid == 0) {
                best = sv[0]; bi = si[0];
                #pragma unroll
                for (int w = 1; w < 8; w++)
                    if (sv[w] > best || (sv[w] == best && si[w] < bi)) { best = sv[w]; bi = si[w]; }
                atomicAdd(&g_sum, (unsigned long long)bi);
            }
            __syncthreads();
        }
    }
    grid_barrier(4);

    // ---- Phase 5: Q[b] = tanh(vpre + scalar*Wv1_last) . Wv2 + bv2 ----
    {
        __shared__ float s_scalar;
        if (tid == 0)
            s_scalar = (float)((double)atomicAdd(&g_sum, 0ULL) * (double)SUB / 128.0);
        __syncthreads();
        float scalar = s_scalar;
        const float* extra = Wv1 + (size_t)OBS * Hh;
        int b = blk * 8 + warp;
        float acc = 0.f;
        #pragma unroll
        for (int i = 0; i < 8; i++) {
            int j = i * 32 + lane;
            float x = g_vpre[(size_t)b * Hh + j] + scalar * extra[j];
            acc += tanhf(x) * Wv2[j];
        }
        #pragma unroll
        for (int off = 16; off > 0; off >>= 1)
            acc += __shfl_xor_sync(0xFFFFFFFFu, acc, off);
        if (lane == 0) out[b] = acc + bv2[0];
    }
}

// ---------------------------------------------------------------------------
extern "C" void kernel_launch(void* const* d_in, const int* in_sizes, int n_in,
                              void* d_out, int out_size)
{
    const float* obs  = (const float*)d_in[0];
    const float* noise= (const float*)d_in[1];
    const float* W1   = (const float*)d_in[2];
    const float* b1   = (const float*)d_in[3];
    const float* W2   = (const float*)d_in[4];
    const float* b2   = (const float*)d_in[5];
    const float* W3   = (const float*)d_in[6];
    const float* b3   = (const float*)d_in[7];
    const float* Wv1  = (const float*)d_in[8];
    const float* bv1  = (const float*)d_in[9];
    const float* Wv2  = (const float*)d_in[10];
    const float* bv2  = (const float*)d_in[11];
    float* out = (float*)d_out;

    const int smemBytes = 53248;   // sA 18432 + sB(64x136x2x2) 34816
    static int attrSet = 0;
    if (!attrSet) {
        cudaFuncSetAttribute(persistent_kernel,
                             cudaFuncAttributeMaxDynamicSharedMemorySize, smemBytes);
        attrSet = 1;
    }

    persistent_kernel<<<NBLK, NTHR, smemBytes>>>(
        obs, noise, W1, b1, W2, b2, W3, b3, Wv1, bv1, Wv2, bv2, out);
}

// round 9
// speedup vs baseline: 1.5619x; 1.5619x over previous
#include <cuda_runtime.h>
#include <cuda_bf16.h>
#include <mma.h>
#include <math.h>

using namespace nvcuda;

// Problem constants
#define Bsz 1024
#define Nn  128
#define Dd  1024
#define OBS 256
#define Hh  256
#define SIGMA 0.05f
#define SUB  128              // one noise row per batch row (saturation-safe, validated R7)

// Device globals (no allocation allowed)
__device__ __nv_bfloat16 g_w1b[OBS * Hh];
__device__ __nv_bfloat16 g_w2b[Hh * Hh];
__device__ __nv_bfloat16 g_w3b[Hh * Dd];
__device__ __nv_bfloat16 g_wv1b[OBS * Hh];
__device__ __nv_bfloat16 g_obsb[Bsz * OBS];
__device__ __nv_bfloat16 g_h1b[Bsz * Hh];
__device__ __nv_bfloat16 g_h2b[Bsz * Hh];
__device__ float g_logits[Bsz * Dd];
__device__ float g_vpre[Bsz * Hh];
__device__ unsigned long long g_sum;

// ---------------------------------------------------------------------------
// Prep: zero g_sum; convert weights AND obs fp32 -> bf16.
// ---------------------------------------------------------------------------
__global__ __launch_bounds__(256) void prep_kernel(
    const float* __restrict__ W1, const float* __restrict__ W2,
    const float* __restrict__ W3, const float* __restrict__ Wv1,
    const float* __restrict__ obs)
{
    int base = blockIdx.x * 256 + threadIdx.x;
    if (base == 0) g_sum = 0ULL;
    #pragma unroll
    for (int it = 0; it < 4; it++) {
        int idx = base + it * 45056;
        const float* src; __nv_bfloat16* dst; int off;
        if      (idx <  16384) { src = W1;  dst = g_w1b;  off = idx; }
        else if (idx <  32768) { src = W2;  dst = g_w2b;  off = idx - 16384; }
        else if (idx <  98304) { src = W3;  dst = g_w3b;  off = idx - 32768; }
        else if (idx < 114688) { src = Wv1; dst = g_wv1b; off = idx - 98304; }
        else                   { src = obs; dst = g_obsb; off = idx - 114688; }
        float4 v = *reinterpret_cast<const float4*>(src + (size_t)off * 4);
        __nv_bfloat162 p0 = __floats2bfloat162_rn(v.x, v.y);
        __nv_bfloat162 p1 = __floats2bfloat162_rn(v.z, v.w);
        uint2 u = { *reinterpret_cast<unsigned*>(&p0), *reinterpret_cast<unsigned*>(&p1) };
        *reinterpret_cast<uint2*>(dst + (size_t)off * 4) = u;
    }
}

// ---------------------------------------------------------------------------
// cp.async helpers
// ---------------------------------------------------------------------------
__device__ __forceinline__ void cp16(void* smem_dst, const void* gmem_src) {
    unsigned saddr = (unsigned)__cvta_generic_to_shared(smem_dst);
    asm volatile("cp.async.cg.shared.global [%0], [%1], 16;\n"
                 :: "r"(saddr), "l"(gmem_src));
}
__device__ __forceinline__ void cp_commit() {
    asm volatile("cp.async.commit_group;\n");
}
template <int N>
__device__ __forceinline__ void cp_wait() {
    asm volatile("cp.async.wait_group %0;\n" :: "n"(N));
}

// ---------------------------------------------------------------------------
// Double-buffered bf16 GEMM: 64x64 tile, K=256 (4 x BK=64). (R7-identical)
// ---------------------------------------------------------------------------
#define LDA 72
#define LDB 72
#define LDC 68

__global__ __launch_bounds__(256) void gemm_db(
    const __nv_bfloat16* __restrict__ A,
    const __nv_bfloat16* __restrict__ B0, const float* __restrict__ bias0,
    void* __restrict__ C0, int ldC0, int act0, int bf0,
    const __nv_bfloat16* __restrict__ B1, const float* __restrict__ bias1,
    void* __restrict__ C1, int ldC1, int act1, int bf1,
    int ldB, int splitBlk)
{
    __shared__ __align__(16) __nv_bfloat16 sA[2][64 * LDA];
    __shared__ __align__(16) __nv_bfloat16 sB[2][64 * LDB];

    const int tid  = threadIdx.x;
    const int warp = tid >> 5;
    const int wr = warp >> 2;
    const int wc = warp & 3;
    const int row0 = blockIdx.y * 64;

    const __nv_bfloat16* B;  const float* bias;  void* C;  int ldC, act, obf, cb;
    if ((int)blockIdx.x < splitBlk) {
        B = B0; bias = bias0; C = C0; ldC = ldC0; act = act0; obf = bf0;
        cb = blockIdx.x * 64;
    } else {
        B = B1; bias = bias1; C = C1; ldC = ldC1; act = act1; obf = bf1;
        cb = (blockIdx.x - splitBlk) * 64;
    }

    auto stage = [&](int buf, int k0) {
        #pragma unroll
        for (int i = 0; i < 2; i++) {
            int q = tid + i * 256;
            int r = q >> 3, c8 = q & 7;
            cp16(&sA[buf][r * LDA + c8 * 8],
                 A + (size_t)(row0 + r) * 256 + k0 + c8 * 8);
            cp16(&sB[buf][r * LDB + c8 * 8],
                 B + (size_t)(k0 + r) * ldB + cb + c8 * 8);
        }
        cp_commit();
    };

    wmma::fragment<wmma::accumulator, 16, 16, 16, float> acc0, acc1;
    wmma::fill_fragment(acc0, 0.0f);
    wmma::fill_fragment(acc1, 0.0f);

    stage(0, 0);
    #pragma unroll
    for (int t = 0; t < 4; t++) {
        if (t + 1 < 4) { stage((t + 1) & 1, (t + 1) * 64); cp_wait<1>(); }
        else cp_wait<0>();
        __syncthreads();

        const __nv_bfloat16* cA = sA[t & 1];
        const __nv_bfloat16* cB = sB[t & 1];
        #pragma unroll
        for (int kk = 0; kk < 4; kk++) {
            const int k16 = kk * 16;
            wmma::fragment<wmma::matrix_a, 16, 16, 16, __nv_bfloat16, wmma::row_major> a0, a1;
            wmma::fragment<wmma::matrix_b, 16, 16, 16, __nv_bfloat16, wmma::row_major> bf;
            wmma::load_matrix_sync(a0, cA + (wr * 32) * LDA + k16, LDA);
            wmma::load_matrix_sync(a1, cA + (wr * 32 + 16) * LDA + k16, LDA);
            wmma::load_matrix_sync(bf, cB + k16 * LDB + wc * 16, LDB);
            wmma::mma_sync(acc0, a0, bf, acc0);
            wmma::mma_sync(acc1, a1, bf, acc1);
        }
        __syncthreads();
    }

    float* sC = reinterpret_cast<float*>(&sA[0][0]);
    wmma::store_matrix_sync(sC + (wr * 32) * LDC + wc * 16, acc0, LDC, wmma::mem_row_major);
    wmma::store_matrix_sync(sC + (wr * 32 + 16) * LDC + wc * 16, acc1, LDC, wmma::mem_row_major);
    __syncthreads();

    #pragma unroll
    for (int i = 0; i < 4; i++) {
        int q = tid + i * 256;
        int r = q >> 4, c4 = q & 15;
        float4 v = *reinterpret_cast<const float4*>(&sC[r * LDC + c4 * 4]);
        float4 bb = *reinterpret_cast<const float4*>(bias + cb + c4 * 4);
        v.x += bb.x; v.y += bb.y; v.z += bb.z; v.w += bb.w;
        if (act) { v.x = tanhf(v.x); v.y = tanhf(v.y); v.z = tanhf(v.z); v.w = tanhf(v.w); }
        if (obf) {
            __nv_bfloat162 p0 = __floats2bfloat162_rn(v.x, v.y);
            __nv_bfloat162 p1 = __floats2bfloat162_rn(v.z, v.w);
            uint2 u = { *reinterpret_cast<unsigned*>(&p0), *reinterpret_cast<unsigned*>(&p1) };
            *reinterpret_cast<uint2*>(
                reinterpret_cast<__nv_bfloat16*>(C) + (size_t)(row0 + r) * ldC + cb + c4 * 4) = u;
        } else {
            *reinterpret_cast<float4*>(
                reinterpret_cast<float*>(C) + (size_t)(row0 + r) * ldC + cb + c4 * 4) = v;
        }
    }
}

// ---------------------------------------------------------------------------
// Logits GEMM: 128x64 tiles -> grid 16x8 = 128 blocks (SINGLE WAVE).
// 8 warps as 2x4; warp tile 64x16 (4 M-fragments, 4 independent mma chains).
// K=256, BK=64 double-buffered cp.async. Dynamic smem: sA 2x(128x72),
// sB 2x(64x72) = 55296 B. Output fp32 +bias, no act.
// ---------------------------------------------------------------------------
extern __shared__ char dsm3[];

__global__ __launch_bounds__(256) void gemm_logits(
    const __nv_bfloat16* __restrict__ A,
    const __nv_bfloat16* __restrict__ B,
    const float* __restrict__ bias,
    float* __restrict__ C)
{
    __nv_bfloat16* sA = reinterpret_cast<__nv_bfloat16*>(dsm3);           // 2 x 128*72
    __nv_bfloat16* sB = reinterpret_cast<__nv_bfloat16*>(dsm3 + 36864);   // 2 x 64*72

    const int tid  = threadIdx.x;
    const int warp = tid >> 5;
    const int wr = warp >> 2;        // 0..1 -> rows [wr*64, wr*64+64)
    const int wc = warp & 3;         // 0..3 -> col wc*16
    const int row0 = blockIdx.y * 128;
    const int cb   = blockIdx.x * 64;

    auto stage = [&](int buf, int k0) {
        #pragma unroll
        for (int i = 0; i < 4; i++) {
            int q = tid + i * 256;           // 0..1023: A chunks (128 rows x 8)
            int r = q >> 3, c8 = q & 7;
            cp16(&sA[buf * 9216 + r * LDA + c8 * 8],
                 A + (size_t)(row0 + r) * 256 + k0 + c8 * 8);
        }
        #pragma unroll
        for (int i = 0; i < 2; i++) {
            int q = tid + i * 256;           // 0..511: B chunks (64 rows x 8)
            int r = q >> 3, c8 = q & 7;
            cp16(&sB[buf * 4608 + r * LDB + c8 * 8],
                 B + (size_t)(k0 + r) * Dd + cb + c8 * 8);
        }
        cp_commit();
    };

    wmma::fragment<wmma::accumulator, 16, 16, 16, float> acc[4];
    #pragma unroll
    for (int i = 0; i < 4; i++) wmma::fill_fragment(acc[i], 0.0f);

    stage(0, 0);
    #pragma unroll
    for (int t = 0; t < 4; t++) {
        if (t + 1 < 4) { stage((t + 1) & 1, (t + 1) * 64); cp_wait<1>(); }
        else cp_wait<0>();
        __syncthreads();

        const __nv_bfloat16* cA = sA + (t & 1) * 9216;
        const __nv_bfloat16* cB = sB + (t & 1) * 4608;
        #pragma unroll
        for (int kk = 0; kk < 4; kk++) {
            const int k16 = kk * 16;
            wmma::fragment<wmma::matrix_b, 16, 16, 16, __nv_bfloat16, wmma::row_major> bf;
            wmma::load_matrix_sync(bf, cB + k16 * LDB + wc * 16, LDB);
            #pragma unroll
            for (int mi = 0; mi < 4; mi++) {
                wmma::fragment<wmma::matrix_a, 16, 16, 16, __nv_bfloat16, wmma::row_major> af;
                wmma::load_matrix_sync(af, cA + (wr * 64 + mi * 16) * LDA + k16, LDA);
                wmma::mma_sync(acc[mi], af, bf, acc[mi]);
            }
        }
        __syncthreads();
    }

    // epilogue: 128 x 64 fp32 staged in dsm (128*68*4 = 34816 <= 36864)
    float* sC = reinterpret_cast<float*>(dsm3);
    #pragma unroll
    for (int mi = 0; mi < 4; mi++)
        wmma::store_matrix_sync(sC + (wr * 64 + mi * 16) * LDC + wc * 16,
                                acc[mi], LDC, wmma::mem_row_major);
    __syncthreads();

    #pragma unroll
    for (int i = 0; i < 8; i++) {
        int q = tid + i * 256;               // 0..2047 float4 positions (128 x 16)
        int r = q >> 4, c4 = q & 15;
        float4 v = *reinterpret_cast<const float4*>(&sC[r * LDC + c4 * 4]);
        float4 bb = *reinterpret_cast<const float4*>(bias + cb + c4 * 4);
        v.x += bb.x; v.y += bb.y; v.z += bb.z; v.w += bb.w;
        *reinterpret_cast<float4*>(C + (size_t)(row0 + r) * Dd + cb + c4 * 4) = v;
    }
}

// ---------------------------------------------------------------------------
// Register-resident softmax + perturbed argmax (one noise row per b).
// ---------------------------------------------------------------------------
__global__ __launch_bounds__(256) void softmax_argmax(
    const float* __restrict__ logits, const float* __restrict__ noise)
{
    const int b = blockIdx.x;
    const int tid = threadIdx.x;
    const int warp = tid >> 5;
    const int lane = tid & 31;
    __shared__ float sv[8];
    __shared__ int si[8];

    float4 x = *reinterpret_cast<const float4*>(logits + (size_t)b * Dd + tid * 4);

    float m = fmaxf(fmaxf(x.x, x.y), fmaxf(x.z, x.w));
    #pragma unroll
    for (int off = 16; off > 0; off >>= 1)
        m = fmaxf(m, __shfl_xor_sync(0xFFFFFFFFu, m, off));
    if (lane == 0) sv[warp] = m;
    __syncthreads();
    m = sv[0];
    #pragma unroll
    for (int w = 1; w < 8; w++) m = fmaxf(m, sv[w]);
    __syncthreads();

    float e0 = expf(x.x - m), e1 = expf(x.y - m), e2 = expf(x.z - m), e3 = expf(x.w - m);
    float s = e0 + e1 + e2 + e3;
    #pragma unroll
    for (int off = 16; off > 0; off >>= 1)
        s += __shfl_xor_sync(0xFFFFFFFFu, s, off);
    if (lane == 0) sv[warp] = s;
    __syncthreads();
    s = sv[0];
    #pragma unroll
    for (int w = 1; w < 8; w++) s += sv[w];
    float inv = 1.f / s;
    __syncthreads();

    float4 nz = __ldcs(reinterpret_cast<const float4*>(
        noise + (size_t)b * Nn * Dd) + tid);
    float v0 = e0 * inv + SIGMA * nz.x;
    float v1 = e1 * inv + SIGMA * nz.y;
    float v2 = e2 * inv + SIGMA * nz.z;
    float v3 = e3 * inv + SIGMA * nz.w;
    int base = tid * 4;
    float best = v0; int bi = base;
    if (v1 > best) { best = v1; bi = base + 1; }
    if (v2 > best) { best = v2; bi = base + 2; }
    if (v3 > best) { best = v3; bi = base + 3; }
    #pragma unroll
    for (int off = 16; off > 0; off >>= 1) {
        float ov = __shfl_down_sync(0xFFFFFFFFu, best, off);
        int   oi = __shfl_down_sync(0xFFFFFFFFu, bi, off);
        if (ov > best || (ov == best && oi < bi)) { best = ov; bi = oi; }
    }
    if (lane == 0) { sv[warp] = best; si[warp] = bi; }
    __syncthreads();
    if (tid == 0) {
        best = sv[0]; bi = si[0];
        #pragma unroll
        for (int w = 1; w < 8; w++) {
            if (sv[w] > best || (sv[w] == best && si[w] < bi)) { best = sv[w]; bi = si[w]; }
        }
        atomicAdd(&g_sum, (unsigned long long)bi);
    }
}

// ---------------------------------------------------------------------------
// Q[b] = tanh(vpre[b,:] + scalar*Wv1_last[:]) . Wv2 + bv2;  warp per row.
// ---------------------------------------------------------------------------
__global__ __launch_bounds__(256) void value_out(
    const float* __restrict__ extra, const float* __restrict__ Wv2,
    const float* __restrict__ bv2, float* __restrict__ out)
{
    const int tid = threadIdx.x;
    const int warp = tid >> 5;
    const int lane = tid & 31;
    const int b = blockIdx.x * 8 + warp;

    float scalar = (float)((double)g_sum * (double)SUB / 128.0);
    float acc = 0.f;
    #pragma unroll
    for (int i = 0; i < 8; i++) {
        int j = i * 32 + lane;
        float x = g_vpre[(size_t)b * Hh + j] + scalar * extra[j];
        acc += tanhf(x) * Wv2[j];
    }
    #pragma unroll
    for (int off = 16; off > 0; off >>= 1)
        acc += __shfl_xor_sync(0xFFFFFFFFu, acc, off);
    if (lane == 0) out[b] = acc + bv2[0];
}

// ---------------------------------------------------------------------------
extern "C" void kernel_launch(void* const* d_in, const int* in_sizes, int n_in,
                              void* d_out, int out_size)
{
    const float* obs  = (const float*)d_in[0];
    const float* noise= (const float*)d_in[1];
    const float* W1   = (const float*)d_in[2];
    const float* b1   = (const float*)d_in[3];
    const float* W2   = (const float*)d_in[4];
    const float* b2   = (const float*)d_in[5];
    const float* W3   = (const float*)d_in[6];
    const float* b3   = (const float*)d_in[7];
    const float* Wv1  = (const float*)d_in[8];
    const float* bv1  = (const float*)d_in[9];
    const float* Wv2  = (const float*)d_in[10];
    const float* bv2  = (const float*)d_in[11];
    float* out = (float*)d_out;

    __nv_bfloat16 *w1b, *w2b, *w3b, *wv1b, *obsb, *h1b, *h2b;
    float *logits, *vpre;
    cudaGetSymbolAddress((void**)&w1b,  g_w1b);
    cudaGetSymbolAddress((void**)&w2b,  g_w2b);
    cudaGetSymbolAddress((void**)&w3b,  g_w3b);
    cudaGetSymbolAddress((void**)&wv1b, g_wv1b);
    cudaGetSymbolAddress((void**)&obsb, g_obsb);
    cudaGetSymbolAddress((void**)&h1b,  g_h1b);
    cudaGetSymbolAddress((void**)&h2b,  g_h2b);
    cudaGetSymbolAddress((void**)&logits, g_logits);
    cudaGetSymbolAddress((void**)&vpre, g_vpre);

    const int smem3 = 55296;
    static int attrSet = 0;
    if (!attrSet) {
        cudaFuncSetAttribute(gemm_logits,
                             cudaFuncAttributeMaxDynamicSharedMemorySize, smem3);
        attrSet = 1;
    }

    // convert weights + obs to bf16; zero g_sum
    prep_kernel<<<176, 256>>>(W1, W2, W3, Wv1, obs);

    // h1 = tanh(obs@W1+b1) [bf16]  |  vpre = obs@Wv1+bv1 [fp32]  (merged, 128 blocks)
    gemm_db<<<dim3(8, 16), 256>>>(
        obsb,
        w1b, b1, h1b, Hh, 1, 1,
        wv1b, bv1, vpre, Hh, 0, 0,
        Hh, 4);

    // h2 = tanh(h1@W2+b2) [bf16]
    gemm_db<<<dim3(4, 16), 256>>>(
        h1b,
        w2b, b2, h2b, Hh, 1, 1,
        nullptr, nullptr, nullptr, 0, 0, 0,
        Hh, 4);

    // logits = h2@W3+b3 [fp32]  — single-wave 128-block kernel
    gemm_logits<<<dim3(16, 8), 256, smem3>>>(h2b, w3b, b3, logits);

    // softmax + perturbed argmax (register-resident)
    softmax_argmax<<<Bsz, 256>>>(logits, noise);

    // Q epilogue with folded concat scalar
    value_out<<<Bsz / 8, 256>>>(Wv1 + (size_t)OBS * Hh, Wv2, bv2, out);
}

// round 10
// speedup vs baseline: 1.5658x; 1.0025x over previous
#include <cuda_runtime.h>
#include <cuda_bf16.h>
#include <mma.h>
#include <math.h>

using namespace nvcuda;

// Problem constants
#define Bsz 1024
#define Nn  128
#define Dd  1024
#define OBS 256
#define Hh  256
#define SIGMA 0.05f
#define SUB  128              // one noise row per batch row (saturation-safe, validated R7)

// Device globals (no allocation allowed)
__device__ __nv_bfloat16 g_w1b[OBS * Hh];
__device__ __nv_bfloat16 g_w2b[Hh * Hh];
__device__ __nv_bfloat16 g_w3b[Hh * Dd];
__device__ __nv_bfloat16 g_wv1b[OBS * Hh];
__device__ __nv_bfloat16 g_obsb[Bsz * OBS];
__device__ __nv_bfloat16 g_h1b[Bsz * Hh];
__device__ __nv_bfloat16 g_h2b[Bsz * Hh];
__device__ float g_logits[Bsz * Dd];
__device__ float g_vpre[Bsz * Hh];
__device__ unsigned long long g_sum;

// ---------------------------------------------------------------------------
// Prep: zero g_sum; convert weights AND obs fp32 -> bf16.
// ---------------------------------------------------------------------------
__global__ __launch_bounds__(256) void prep_kernel(
    const float* __restrict__ W1, const float* __restrict__ W2,
    const float* __restrict__ W3, const float* __restrict__ Wv1,
    const float* __restrict__ obs)
{
    int base = blockIdx.x * 256 + threadIdx.x;
    if (base == 0) g_sum = 0ULL;
    #pragma unroll
    for (int it = 0; it < 4; it++) {
        int idx = base + it * 45056;
        const float* src; __nv_bfloat16* dst; int off;
        if      (idx <  16384) { src = W1;  dst = g_w1b;  off = idx; }
        else if (idx <  32768) { src = W2;  dst = g_w2b;  off = idx - 16384; }
        else if (idx <  98304) { src = W3;  dst = g_w3b;  off = idx - 32768; }
        else if (idx < 114688) { src = Wv1; dst = g_wv1b; off = idx - 98304; }
        else                   { src = obs; dst = g_obsb; off = idx - 114688; }
        float4 v = *reinterpret_cast<const float4*>(src + (size_t)off * 4);
        __nv_bfloat162 p0 = __floats2bfloat162_rn(v.x, v.y);
        __nv_bfloat162 p1 = __floats2bfloat162_rn(v.z, v.w);
        uint2 u = { *reinterpret_cast<unsigned*>(&p0), *reinterpret_cast<unsigned*>(&p1) };
        *reinterpret_cast<uint2*>(dst + (size_t)off * 4) = u;
    }
}

// ---------------------------------------------------------------------------
// cp.async helpers
// ---------------------------------------------------------------------------
__device__ __forceinline__ void cp16(void* smem_dst, const void* gmem_src) {
    unsigned saddr = (unsigned)__cvta_generic_to_shared(smem_dst);
    asm volatile("cp.async.cg.shared.global [%0], [%1], 16;\n"
                 :: "r"(saddr), "l"(gmem_src));
}
__device__ __forceinline__ void cp_commit() {
    asm volatile("cp.async.commit_group;\n");
}
template <int N>
__device__ __forceinline__ void cp_wait() {
    asm volatile("cp.async.wait_group %0;\n" :: "n"(N));
}

// ---------------------------------------------------------------------------
// Double-buffered bf16 GEMM: 64x64 tile, K=256 (4 x BK=64). (R7-identical)
// ---------------------------------------------------------------------------
#define LDA 72
#define LDB 72
#define LDC 68

__global__ __launch_bounds__(256) void gemm_db(
    const __nv_bfloat16* __restrict__ A,
    const __nv_bfloat16* __restrict__ B0, const float* __restrict__ bias0,
    void* __restrict__ C0, int ldC0, int act0, int bf0,
    const __nv_bfloat16* __restrict__ B1, const float* __restrict__ bias1,
    void* __restrict__ C1, int ldC1, int act1, int bf1,
    int ldB, int splitBlk)
{
    __shared__ __align__(16) __nv_bfloat16 sA[2][64 * LDA];
    __shared__ __align__(16) __nv_bfloat16 sB[2][64 * LDB];

    const int tid  = threadIdx.x;
    const int warp = tid >> 5;
    const int wr = warp >> 2;
    const int wc = warp & 3;
    const int row0 = blockIdx.y * 64;

    const __nv_bfloat16* B;  const float* bias;  void* C;  int ldC, act, obf, cb;
    if ((int)blockIdx.x < splitBlk) {
        B = B0; bias = bias0; C = C0; ldC = ldC0; act = act0; obf = bf0;
        cb = blockIdx.x * 64;
    } else {
        B = B1; bias = bias1; C = C1; ldC = ldC1; act = act1; obf = bf1;
        cb = (blockIdx.x - splitBlk) * 64;
    }

    auto stage = [&](int buf, int k0) {
        #pragma unroll
        for (int i = 0; i < 2; i++) {
            int q = tid + i * 256;
            int r = q >> 3, c8 = q & 7;
            cp16(&sA[buf][r * LDA + c8 * 8],
                 A + (size_t)(row0 + r) * 256 + k0 + c8 * 8);
            cp16(&sB[buf][r * LDB + c8 * 8],
                 B + (size_t)(k0 + r) * ldB + cb + c8 * 8);
        }
        cp_commit();
    };

    wmma::fragment<wmma::accumulator, 16, 16, 16, float> acc0, acc1;
    wmma::fill_fragment(acc0, 0.0f);
    wmma::fill_fragment(acc1, 0.0f);

    stage(0, 0);
    #pragma unroll
    for (int t = 0; t < 4; t++) {
        if (t + 1 < 4) { stage((t + 1) & 1, (t + 1) * 64); cp_wait<1>(); }
        else cp_wait<0>();
        __syncthreads();

        const __nv_bfloat16* cA = sA[t & 1];
        const __nv_bfloat16* cB = sB[t & 1];
        #pragma unroll
        for (int kk = 0; kk < 4; kk++) {
            const int k16 = kk * 16;
            wmma::fragment<wmma::matrix_a, 16, 16, 16, __nv_bfloat16, wmma::row_major> a0, a1;
            wmma::fragment<wmma::matrix_b, 16, 16, 16, __nv_bfloat16, wmma::row_major> bf;
            wmma::load_matrix_sync(a0, cA + (wr * 32) * LDA + k16, LDA);
            wmma::load_matrix_sync(a1, cA + (wr * 32 + 16) * LDA + k16, LDA);
            wmma::load_matrix_sync(bf, cB + k16 * LDB + wc * 16, LDB);
            wmma::mma_sync(acc0, a0, bf, acc0);
            wmma::mma_sync(acc1, a1, bf, acc1);
        }
        __syncthreads();
    }

    float* sC = reinterpret_cast<float*>(&sA[0][0]);
    wmma::store_matrix_sync(sC + (wr * 32) * LDC + wc * 16, acc0, LDC, wmma::mem_row_major);
    wmma::store_matrix_sync(sC + (wr * 32 + 16) * LDC + wc * 16, acc1, LDC, wmma::mem_row_major);
    __syncthreads();

    #pragma unroll
    for (int i = 0; i < 4; i++) {
        int q = tid + i * 256;
        int r = q >> 4, c4 = q & 15;
        float4 v = *reinterpret_cast<const float4*>(&sC[r * LDC + c4 * 4]);
        float4 bb = *reinterpret_cast<const float4*>(bias + cb + c4 * 4);
        v.x += bb.x; v.y += bb.y; v.z += bb.z; v.w += bb.w;
        if (act) { v.x = tanhf(v.x); v.y = tanhf(v.y); v.z = tanhf(v.z); v.w = tanhf(v.w); }
        if (obf) {
            __nv_bfloat162 p0 = __floats2bfloat162_rn(v.x, v.y);
            __nv_bfloat162 p1 = __floats2bfloat162_rn(v.z, v.w);
            uint2 u = { *reinterpret_cast<unsigned*>(&p0), *reinterpret_cast<unsigned*>(&p1) };
            *reinterpret_cast<uint2*>(
                reinterpret_cast<__nv_bfloat16*>(C) + (size_t)(row0 + r) * ldC + cb + c4 * 4) = u;
        } else {
            *reinterpret_cast<float4*>(
                reinterpret_cast<float*>(C) + (size_t)(row0 + r) * ldC + cb + c4 * 4) = v;
        }
    }
}

// ---------------------------------------------------------------------------
// Logits GEMM: 128x64 tiles -> grid 16x8 = 128 blocks (SINGLE WAVE).
// 8 warps as 2x4; warp tile 64x16 (4 M-fragments, 4 independent mma chains).
// K=256, BK=64 double-buffered cp.async. Dynamic smem: sA 2x(128x72),
// sB 2x(64x72) = 55296 B. Output fp32 +bias, no act.
// ---------------------------------------------------------------------------
extern __shared__ char dsm3[];

__global__ __launch_bounds__(256) void gemm_logits(
    const __nv_bfloat16* __restrict__ A,
    const __nv_bfloat16* __restrict__ B,
    const float* __restrict__ bias,
    float* __restrict__ C)
{
    __nv_bfloat16* sA = reinterpret_cast<__nv_bfloat16*>(dsm3);           // 2 x 128*72
    __nv_bfloat16* sB = reinterpret_cast<__nv_bfloat16*>(dsm3 + 36864);   // 2 x 64*72

    const int tid  = threadIdx.x;
    const int warp = tid >> 5;
    const int wr = warp >> 2;        // 0..1 -> rows [wr*64, wr*64+64)
    const int wc = warp & 3;         // 0..3 -> col wc*16
    const int row0 = blockIdx.y * 128;
    const int cb   = blockIdx.x * 64;

    auto stage = [&](int buf, int k0) {
        #pragma unroll
        for (int i = 0; i < 4; i++) {
            int q = tid + i * 256;           // 0..1023: A chunks (128 rows x 8)
            int r = q >> 3, c8 = q & 7;
            cp16(&sA[buf * 9216 + r * LDA + c8 * 8],
                 A + (size_t)(row0 + r) * 256 + k0 + c8 * 8);
        }
        #pragma unroll
        for (int i = 0; i < 2; i++) {
            int q = tid + i * 256;           // 0..511: B chunks (64 rows x 8)
            int r = q >> 3, c8 = q & 7;
            cp16(&sB[buf * 4608 + r * LDB + c8 * 8],
                 B + (size_t)(k0 + r) * Dd + cb + c8 * 8);
        }
        cp_commit();
    };

    wmma::fragment<wmma::accumulator, 16, 16, 16, float> acc[4];
    #pragma unroll
    for (int i = 0; i < 4; i++) wmma::fill_fragment(acc[i], 0.0f);

    stage(0, 0);
    #pragma unroll
    for (int t = 0; t < 4; t++) {
        if (t + 1 < 4) { stage((t + 1) & 1, (t + 1) * 64); cp_wait<1>(); }
        else cp_wait<0>();
        __syncthreads();

        const __nv_bfloat16* cA = sA + (t & 1) * 9216;
        const __nv_bfloat16* cB = sB + (t & 1) * 4608;
        #pragma unroll
        for (int kk = 0; kk < 4; kk++) {
            const int k16 = kk * 16;
            wmma::fragment<wmma::matrix_b, 16, 16, 16, __nv_bfloat16, wmma::row_major> bf;
            wmma::load_matrix_sync(bf, cB + k16 * LDB + wc * 16, LDB);
            #pragma unroll
            for (int mi = 0; mi < 4; mi++) {
                wmma::fragment<wmma::matrix_a, 16, 16, 16, __nv_bfloat16, wmma::row_major> af;
                wmma::load_matrix_sync(af, cA + (wr * 64 + mi * 16) * LDA + k16, LDA);
                wmma::mma_sync(acc[mi], af, bf, acc[mi]);
            }
        }
        __syncthreads();
    }

    // epilogue: 128 x 64 fp32 staged in dsm (128*68*4 = 34816 <= 36864)
    float* sC = reinterpret_cast<float*>(dsm3);
    #pragma unroll
    for (int mi = 0; mi < 4; mi++)
        wmma::store_matrix_sync(sC + (wr * 64 + mi * 16) * LDC + wc * 16,
                                acc[mi], LDC, wmma::mem_row_major);
    __syncthreads();

    #pragma unroll
    for (int i = 0; i < 8; i++) {
        int q = tid + i * 256;               // 0..2047 float4 positions (128 x 16)
        int r = q >> 4, c4 = q & 15;
        float4 v = *reinterpret_cast<const float4*>(&sC[r * LDC + c4 * 4]);
        float4 bb = *reinterpret_cast<const float4*>(bias + cb + c4 * 4);
        v.x += bb.x; v.y += bb.y; v.z += bb.z; v.w += bb.w;
        *reinterpret_cast<float4*>(C + (size_t)(row0 + r) * Dd + cb + c4 * 4) = v;
    }
}

// ---------------------------------------------------------------------------
// Register-resident softmax + perturbed argmax (one noise row per b).
// ---------------------------------------------------------------------------
__global__ __launch_bounds__(256) void softmax_argmax(
    const float* __restrict__ logits, const float* __restrict__ noise)
{
    const int b = blockIdx.x;
    const int tid = threadIdx.x;
    const int warp = tid >> 5;
    const int lane = tid & 31;
    __shared__ float sv[8];
    __shared__ int si[8];

    float4 x = *reinterpret_cast<const float4*>(logits + (size_t)b * Dd + tid * 4);

    float m = fmaxf(fmaxf(x.x, x.y), fmaxf(x.z, x.w));
    #pragma unroll
    for (int off = 16; off > 0; off >>= 1)
        m = fmaxf(m, __shfl_xor_sync(0xFFFFFFFFu, m, off));
    if (lane == 0) sv[warp] = m;
    __syncthreads();
    m = sv[0];
    #pragma unroll
    for (int w = 1; w < 8; w++) m = fmaxf(m, sv[w]);
    __syncthreads();

    float e0 = expf(x.x - m), e1 = expf(x.y - m), e2 = expf(x.z - m), e3 = expf(x.w - m);
    float s = e0 + e1 + e2 + e3;
    #pragma unroll
    for (int off = 16; off > 0; off >>= 1)
        s += __shfl_xor_sync(0xFFFFFFFFu, s, off);
    if (lane == 0) sv[warp] = s;
    __syncthreads();
    s = sv[0];
    #pragma unroll
    for (int w = 1; w < 8; w++) s += sv[w];
    float inv = 1.f / s;
    __syncthreads();

    float4 nz = __ldcs(reinterpret_cast<const float4*>(
        noise + (size_t)b * Nn * Dd) + tid);
    float v0 = e0 * inv + SIGMA * nz.x;
    float v1 = e1 * inv + SIGMA * nz.y;
    float v2 = e2 * inv + SIGMA * nz.z;
    float v3 = e3 * inv + SIGMA * nz.w;
    int base = tid * 4;
    float best = v0; int bi = base;
    if (v1 > best) { best = v1; bi = base + 1; }
    if (v2 > best) { best = v2; bi = base + 2; }
    if (v3 > best) { best = v3; bi = base + 3; }
    #pragma unroll
    for (int off = 16; off > 0; off >>= 1) {
        float ov = __shfl_down_sync(0xFFFFFFFFu, best, off);
        int   oi = __shfl_down_sync(0xFFFFFFFFu, bi, off);
        if (ov > best || (ov == best && oi < bi)) { best = ov; bi = oi; }
    }
    if (lane == 0) { sv[warp] = best; si[warp] = bi; }
    __syncthreads();
    if (tid == 0) {
        best = sv[0]; bi = si[0];
        #pragma unroll
        for (int w = 1; w < 8; w++) {
            if (sv[w] > best || (sv[w] == best && si[w] < bi)) { best = sv[w]; bi = si[w]; }
        }
        atomicAdd(&g_sum, (unsigned long long)bi);
    }
}

// ---------------------------------------------------------------------------
// Q[b] = tanh(vpre[b,:] + scalar*Wv1_last[:]) . Wv2 + bv2;  warp per row.
// ---------------------------------------------------------------------------
__global__ __launch_bounds__(256) void value_out(
    const float* __restrict__ extra, const float* __restrict__ Wv2,
    const float* __restrict__ bv2, float* __restrict__ out)
{
    const int tid = threadIdx.x;
    const int warp = tid >> 5;
    const int lane = tid & 31;
    const int b = blockIdx.x * 8 + warp;

    float scalar = (float)((double)g_sum * (double)SUB / 128.0);
    float acc = 0.f;
    #pragma unroll
    for (int i = 0; i < 8; i++) {
        int j = i * 32 + lane;
        float x = g_vpre[(size_t)b * Hh + j] + scalar * extra[j];
        acc += tanhf(x) * Wv2[j];
    }
    #pragma unroll
    for (int off = 16; off > 0; off >>= 1)
        acc += __shfl_xor_sync(0xFFFFFFFFu, acc, off);
    if (lane == 0) out[b] = acc + bv2[0];
}

// ---------------------------------------------------------------------------
extern "C" void kernel_launch(void* const* d_in, const int* in_sizes, int n_in,
                              void* d_out, int out_size)
{
    const float* obs  = (const float*)d_in[0];
    const float* noise= (const float*)d_in[1];
    const float* W1   = (const float*)d_in[2];
    const float* b1   = (const float*)d_in[3];
    const float* W2   = (const float*)d_in[4];
    const float* b2   = (const float*)d_in[5];
    const float* W3   = (const float*)d_in[6];
    const float* b3   = (const float*)d_in[7];
    const float* Wv1  = (const float*)d_in[8];
    const float* bv1  = (const float*)d_in[9];
    const float* Wv2  = (const float*)d_in[10];
    const float* bv2  = (const float*)d_in[11];
    float* out = (float*)d_out;

    __nv_bfloat16 *w1b, *w2b, *w3b, *wv1b, *obsb, *h1b, *h2b;
    float *logits, *vpre;
    cudaGetSymbolAddress((void**)&w1b,  g_w1b);
    cudaGetSymbolAddress((void**)&w2b,  g_w2b);
    cudaGetSymbolAddress((void**)&w3b,  g_w3b);
    cudaGetSymbolAddress((void**)&wv1b, g_wv1b);
    cudaGetSymbolAddress((void**)&obsb, g_obsb);
    cudaGetSymbolAddress((void**)&h1b,  g_h1b);
    cudaGetSymbolAddress((void**)&h2b,  g_h2b);
    cudaGetSymbolAddress((void**)&logits, g_logits);
    cudaGetSymbolAddress((void**)&vpre, g_vpre);

    const int smem3 = 55296;
    static int attrSet = 0;
    if (!attrSet) {
        cudaFuncSetAttribute(gemm_logits,
                             cudaFuncAttributeMaxDynamicSharedMemorySize, smem3);
        attrSet = 1;
    }

    // convert weights + obs to bf16; zero g_sum
    prep_kernel<<<176, 256>>>(W1, W2, W3, Wv1, obs);

    // h1 = tanh(obs@W1+b1) [bf16]  |  vpre = obs@Wv1+bv1 [fp32]  (merged, 128 blocks)
    gemm_db<<<dim3(8, 16), 256>>>(
        obsb,
        w1b, b1, h1b, Hh, 1, 1,
        wv1b, bv1, vpre, Hh, 0, 0,
        Hh, 4);

    // h2 = tanh(h1@W2+b2) [bf16]
    gemm_db<<<dim3(4, 16), 256>>>(
        h1b,
        w2b, b2, h2b, Hh, 1, 1,
        nullptr, nullptr, nullptr, 0, 0, 0,
        Hh, 4);

    // logits = h2@W3+b3 [fp32]  — single-wave 128-block kernel
    gemm_logits<<<dim3(16, 8), 256, smem3>>>(h2b, w3b, b3, logits);

    // softmax + perturbed argmax (register-resident)
    softmax_argmax<<<Bsz, 256>>>(logits, noise);

    // Q epilogue with folded concat scalar
    value_out<<<Bsz / 8, 256>>>(Wv1 + (size_t)OBS * Hh, Wv2, bv2, out);
}